// round 17
// baseline (speedup 1.0000x reference)
#include <cuda_runtime.h>

// inputs [B=8, T=4096, C=1024] fp32 -> out[b,t,c] = mean over s<=t of in[b,s,c]
//
// SINGLE-PASS decoupled-lookback scan.
//  Liveness : ticket ordering (atomicAdd per chain) -> seg order == CTA start
//             order -> all predecessors resident/done -> spins bounded.
//  Safety   : per-lane packed {flag,value} 8-byte word, published with ONE
//             relaxed 64-bit store. Value travels with flag -> no fences, no
//             cross-thread visibility hazards (each lane reads/writes only
//             its own column's words). flag: 0 empty, 1 aggregate, 2 inclusive.
// Traffic: 134 MB in + 134 MB out + ~12 MB state (state fits L2).

#define B_DIM   8
#define T_DIM   4096
#define C_DIM   1024
#define CQ      (C_DIM / 4)            // 256 float4 per row
#define CT      128                    // threads per CTA, one float4 column each
#define CTILES  (CQ / CT)              // 2
#define NCHAIN  (B_DIM * CTILES)       // 16 independent scan chains
#define SEGLEN  16                     // rows per CTA (16 float4 in registers)
#define NSEG    (T_DIM / SEGLEN)       // 256 segments per chain

// Per-lane packed state: 4 words per (chain,seg,lane) column = x/y/z/w of the
// float4. 16*256*128*4 * 8 B = 16 MB... too big; instead pack per float4 lane
// component separately would 4x the words. We keep ONE word per float SCALAR
// column is too much; so: 4 words per lane (one per component).
// 16 chains * 256 segs * 128 lanes * 4 comps * 8 B = 16 MB. L2 is 126 MB: OK,
// but init cost matters -> use 4 separate words per lane packed as ulonglong4
// would lose single-store atomicity per component; component words are
// independent (each is its own scalar protocol), so 4 relaxed b64 stores/lane.
__device__ unsigned long long g_state[NCHAIN * NSEG * CT * 4];
__device__ int g_ticket[NCHAIN];

__device__ __forceinline__ void st_word(unsigned long long* p, float v, unsigned flag) {
    unsigned long long w = ((unsigned long long)__float_as_uint(v) << 32)
                         | (unsigned long long)flag;
    asm volatile("st.relaxed.gpu.global.b64 [%0], %1;" :: "l"(p), "l"(w) : "memory");
}

__device__ __forceinline__ unsigned long long ld_word(const unsigned long long* p) {
    unsigned long long w;
    asm volatile("ld.relaxed.gpu.global.b64 %0, [%1];" : "=l"(w) : "l"(p) : "memory");
    return w;
}

__global__ __launch_bounds__(256) void init_kernel() {
    const int i = blockIdx.x * blockDim.x + threadIdx.x;
    ulonglong2* p = reinterpret_cast<ulonglong2*>(g_state);
    if (i < NCHAIN * NSEG * CT * 2) p[i] = make_ulonglong2(0ull, 0ull);
    if (i < NCHAIN) g_ticket[i] = 0;
}

__global__ __launch_bounds__(CT) void scan_kernel(const float* __restrict__ in,
                                                  float* __restrict__ out) {
    const int chain = blockIdx.z * CTILES + blockIdx.y;
    const int cq    = blockIdx.y * CT + threadIdx.x;
    const int b     = blockIdx.z;

    __shared__ int s_seg;
    if (threadIdx.x == 0)
        s_seg = atomicAdd(&g_ticket[chain], 1);     // ticket = start order
    __syncthreads();
    const int seg = s_seg;
    if (seg >= NSEG) return;                        // defensive: never true
    const int t0 = seg * SEGLEN;

    const float4* pin = reinterpret_cast<const float4*>(
        in + ((size_t)b * T_DIM + t0) * C_DIM) + cq;

    float4 r[SEGLEN];
#pragma unroll
    for (int t = 0; t < SEGLEN; ++t)
        r[t] = pin[(size_t)t * CQ];
#pragma unroll
    for (int t = 1; t < SEGLEN; ++t) {
        r[t].x += r[t-1].x; r[t].y += r[t-1].y;
        r[t].z += r[t-1].z; r[t].w += r[t-1].w;
    }
    const float4 agg = r[SEGLEN - 1];

    // My 4 component words, consecutive: index = ((chain*NSEG+seg)*CT+lane)*4+k
    unsigned long long* my = &g_state[(size_t)((chain * NSEG + seg) * CT + threadIdx.x) * 4];

    if (seg == 0) {
        st_word(my + 0, agg.x, 2u); st_word(my + 1, agg.y, 2u);
        st_word(my + 2, agg.z, 2u); st_word(my + 3, agg.w, 2u);
    } else {
        st_word(my + 0, agg.x, 1u); st_word(my + 1, agg.y, 1u);
        st_word(my + 2, agg.z, 1u); st_word(my + 3, agg.w, 1u);
    }

    // Per-lane decoupled lookback (no block syncs). Each component word is an
    // independent scalar protocol; process all 4 in lockstep per predecessor.
    float4 ex = make_float4(0.f, 0.f, 0.f, 0.f);
    if (seg > 0) {
        const size_t lanebase = (size_t)(chain * NSEG) * CT * 4 + (size_t)threadIdx.x * 4;
        int p = seg - 1;
        for (;;) {
            const unsigned long long* pw =
                &g_state[lanebase + (size_t)p * (CT * 4)];
            unsigned long long wx, wy, wz, ww;
            // spin until all 4 component words of predecessor p are published;
            // p started before us (ticket) -> bounded.
            do { wx = ld_word(pw + 0); } while ((unsigned)wx == 0u);
            do { wy = ld_word(pw + 1); } while ((unsigned)wy == 0u);
            do { wz = ld_word(pw + 2); } while ((unsigned)wz == 0u);
            do { ww = ld_word(pw + 3); } while ((unsigned)ww == 0u);
            ex.x += __uint_as_float((unsigned)(wx >> 32));
            ex.y += __uint_as_float((unsigned)(wy >> 32));
            ex.z += __uint_as_float((unsigned)(wz >> 32));
            ex.w += __uint_as_float((unsigned)(ww >> 32));
            // stop when this lane's x-word shows inclusive; components of one
            // lane are always published with the same flag by their owner,
            // except during upgrade 1->2 (mixed agg/inc reads would double-
            // count), so decide on ALL four: only stop if all are inclusive;
            // if mixed, we already added some inclusive values -> must NOT
            // continue. Avoid by deciding on the minimum flag BEFORE adding:
            // (handled below by re-reading when mixed)
            unsigned fmin = (unsigned)wx;
            fmin = min(fmin, (unsigned)wy);
            fmin = min(fmin, (unsigned)wz);
            fmin = min(fmin, (unsigned)ww);
            unsigned fmax = (unsigned)wx;
            fmax = max(fmax, (unsigned)wy);
            fmax = max(fmax, (unsigned)wz);
            fmax = max(fmax, (unsigned)ww);
            if (fmin != fmax) {
                // mixed snapshot: roll back and retry this predecessor until
                // consistent (upgrade completes quickly; bounded).
                ex.x -= __uint_as_float((unsigned)(wx >> 32));
                ex.y -= __uint_as_float((unsigned)(wy >> 32));
                ex.z -= __uint_as_float((unsigned)(wz >> 32));
                ex.w -= __uint_as_float((unsigned)(ww >> 32));
                continue;
            }
            if (fmin == 2u) break;
            --p;
        }
    }

    // Publish inclusive (upgrade 1 -> 2).
    if (seg > 0) {
        st_word(my + 0, agg.x + ex.x, 2u);
        st_word(my + 1, agg.y + ex.y, 2u);
        st_word(my + 2, agg.z + ex.z, 2u);
        st_word(my + 3, agg.w + ex.w, 2u);
    }

    // Emit: (local prefix + carry) * rcp(t+1). MUFU count: 16 per thread
    // per CTA -> 2M total, ~1.3us MUFU budget chip-wide; acceptable without
    // a smem table (avoids an extra __syncthreads after early return path).
    float4* pout = reinterpret_cast<float4*>(
        out + ((size_t)b * T_DIM + t0) * C_DIM) + cq;
#pragma unroll
    for (int t = 0; t < SEGLEN; ++t) {
        const float rr = __frcp_rn((float)(t0 + t + 1));
        float4 o = r[t];
        o.x = (o.x + ex.x) * rr; o.y = (o.y + ex.y) * rr;
        o.z = (o.z + ex.z) * rr; o.w = (o.w + ex.w) * rr;
        pout[(size_t)t * CQ] = o;
    }
}

extern "C" void kernel_launch(void* const* d_in, const int* in_sizes, int n_in,
                              void* d_out, int out_size) {
    (void)in_sizes; (void)n_in; (void)out_size;
    const float* in = (const float*)d_in[0];
    float* out = (float*)d_out;

    const int nvec = NCHAIN * NSEG * CT * 2;        // ulonglong2 count
    init_kernel<<<(nvec + 255) / 256, 256>>>();

    dim3 grid(NSEG, CTILES, B_DIM);                 // 256 x 2 x 8 = 4096 CTAs
    scan_kernel<<<grid, CT>>>(in, out);
}